// round 3
// baseline (speedup 1.0000x reference)
#include <cuda_runtime.h>

// GSA_69063074119914 — scalar-channel spatial-reduction attention, tabulated.
// d=1 => out[b,s] = f_b(q_s); tabulate f_b, f_b' per batch on the exact q-range,
// evaluate queries with cubic Hermite. Range scan fully parallelized.

#define NB    16
#define NT    256      // keys per batch
#define HW    16384    // queries per batch
#define NPTS  1024     // table nodes per batch
#define NSL   16       // range-scan slices per batch
#define LOG2E 1.4426950408889634f
#define LN2   0.6931471805599453f

// Device-global scratch (no allocation allowed in kernel_launch).
__device__ float2 g_kv[NB][NT];       // x = k*log2(e), y = v
__device__ float2 g_mm[NB];           // x = max(k2), y = min(k2)
__device__ float2 g_part[NB][NSL];    // per-slice (xmin, xmax)
__device__ float2 g_tab[NB][NPTS];    // x = f(q_n), y = f'(q_n)

// Redundant per-block final reduction of the 16 slice partials -> (qlo, qhi).
__device__ __forceinline__ float2 load_qrange(int b, float wq0, float bq0)
{
    float xmn = g_part[b][0].x, xmx = g_part[b][0].y;
#pragma unroll
    for (int i = 1; i < NSL; ++i) {
        float2 p = g_part[b][i];
        xmn = fminf(xmn, p.x);
        xmx = fmaxf(xmx, p.y);
    }
    const float q1 = fmaf(wq0, xmn, bq0);
    const float q2 = fmaf(wq0, xmx, bq0);
    return make_float2(fminf(q1, q2), fmaxf(q1, q2));
}

// ---------------------------------------------------------------------------
// Kernel 1: grid (NSL+1, NB).
//   blockIdx.x < NSL : min/max scan of one 1024-float slice of x[b]
//   blockIdx.x == NSL: conv8x8/s8 -> (k,v), k2 min/max
__global__ void __launch_bounds__(256) gsa_prep_kernel(
        const float* __restrict__ x,
        const float* __restrict__ wk, const float* __restrict__ bk,
        const float* __restrict__ wv, const float* __restrict__ bv,
        const float* __restrict__ cw, const float* __restrict__ cb)
{
    const int b    = blockIdx.y;
    const int role = blockIdx.x;
    const int t    = threadIdx.x;
    const int lane = t & 31;
    const int warp = t >> 5;

    if (role < NSL) {
        // ---- range scan: 256 threads x float4 = 1024 floats ----
        const float4 v = *(const float4*)(x + (size_t)b * HW + role * 1024 + t * 4);
        float mn = fminf(fminf(v.x, v.y), fminf(v.z, v.w));
        float mx = fmaxf(fmaxf(v.x, v.y), fmaxf(v.z, v.w));
#pragma unroll
        for (int off = 16; off > 0; off >>= 1) {
            mn = fminf(mn, __shfl_xor_sync(0xffffffffu, mn, off));
            mx = fmaxf(mx, __shfl_xor_sync(0xffffffffu, mx, off));
        }
        __shared__ float smn[8], smx[8];
        if (lane == 0) { smn[warp] = mn; smx[warp] = mx; }
        __syncthreads();
        if (t == 0) {
            float rmn = smn[0], rmx = smx[0];
#pragma unroll
            for (int w = 1; w < 8; ++w) {
                rmn = fminf(rmn, smn[w]);
                rmx = fmaxf(rmx, smx[w]);
            }
            g_part[b][role] = make_float2(rmn, rmx);
        }
        return;
    }

    // ---- conv block ----
    __shared__ float s_cw[64];
    __shared__ float s_mx[8], s_mn[8];
    if (t < 64) s_cw[t] = cw[t];
    __syncthreads();

    const int i = t >> 4;
    const int j = t & 15;
    const float* xb = x + (size_t)b * HW + (i * 8) * 128 + j * 8;
    float ds = 0.f;
#pragma unroll
    for (int p = 0; p < 8; ++p)
#pragma unroll
        for (int q = 0; q < 8; ++q)
            ds = fmaf(xb[p * 128 + q], s_cw[p * 8 + q], ds);
    ds += cb[0];

    const float k2 = fmaf(wk[0], ds, bk[0]) * LOG2E;
    const float v  = fmaf(wv[0], ds, bv[0]);
    g_kv[b][t] = make_float2(k2, v);

    float kmx = k2, kmn = k2;
#pragma unroll
    for (int off = 16; off > 0; off >>= 1) {
        kmx = fmaxf(kmx, __shfl_xor_sync(0xffffffffu, kmx, off));
        kmn = fminf(kmn, __shfl_xor_sync(0xffffffffu, kmn, off));
    }
    if (lane == 0) { s_mx[warp] = kmx; s_mn[warp] = kmn; }
    __syncthreads();
    if (t == 0) {
        float rmx = s_mx[0], rmn = s_mn[0];
#pragma unroll
        for (int w = 1; w < 8; ++w) {
            rmx = fmaxf(rmx, s_mx[w]);
            rmn = fminf(rmn, s_mn[w]);
        }
        g_mm[b] = make_float2(rmx, rmn);
    }
}

// ---------------------------------------------------------------------------
// Kernel 2: build f/f' table. grid (NPTS/256, NB).
__global__ void __launch_bounds__(256) gsa_table_kernel(
        const float* __restrict__ wq, const float* __restrict__ bq)
{
    __shared__ float2 s_kv[NT];
    const int b = blockIdx.y;
    const int t = threadIdx.x;

    s_kv[t] = g_kv[b][t];

    const float2 qr = load_qrange(b, wq[0], bq[0]);
    const float2 mm = g_mm[b];
    __syncthreads();

    const int   n  = blockIdx.x * 256 + t;
    const float h  = (qr.y - qr.x) * (1.0f / (NPTS - 1));
    const float qn = qr.x + h * (float)n;
    const float m2 = fmaxf(qn * mm.x, qn * mm.y);   // exact max exponent

    float S0 = 0.f, S1 = 0.f, S2 = 0.f, S3 = 0.f;
#pragma unroll 8
    for (int u = 0; u < NT; ++u) {
        float2 kv = s_kv[u];
        float a = fmaf(qn, kv.x, -m2);
        float e;
        asm("ex2.approx.f32 %0, %1;" : "=f"(e) : "f"(a));
        float ve = kv.y * e;
        S0 += e;
        S1 += ve;
        S2 = fmaf(kv.x, e,  S2);
        S3 = fmaf(kv.x, ve, S3);
    }
    const float r  = __frcp_rn(S0);
    const float f  = S1 * r;
    const float fp = LN2 * r * fmaf(-f, S2, S3);   // df/dq
    g_tab[b][n] = make_float2(f, fp);
}

// ---------------------------------------------------------------------------
// Kernel 3: evaluate queries, 4 per thread. grid (HW/1024, NB).
__global__ void __launch_bounds__(256) gsa_query_kernel(
        const float* __restrict__ x,
        const float* __restrict__ wq, const float* __restrict__ bq,
        float* __restrict__ out)
{
    const int b = blockIdx.y;
    const int t = threadIdx.x;
    const float wq0 = wq[0], bq0 = bq[0];

    const float2 qr    = load_qrange(b, wq0, bq0);
    const float  range = qr.y - qr.x;
    const float  hstep = range * (1.0f / (NPTS - 1));
    const float  scale = (range > 0.f) ? (NPTS - 1) / range : 0.f;

    const size_t base = (size_t)b * HW + blockIdx.x * 1024 + t * 4;
    const float4 xv   = *(const float4*)(x + base);

    float qs[4] = { fmaf(wq0, xv.x, bq0), fmaf(wq0, xv.y, bq0),
                    fmaf(wq0, xv.z, bq0), fmaf(wq0, xv.w, bq0) };
    float res[4];
#pragma unroll
    for (int e = 0; e < 4; ++e) {
        float tpos = (qs[e] - qr.x) * scale;
        tpos = fminf(fmaxf(tpos, 0.f), (float)(NPTS - 1));
        int i = min((int)tpos, NPTS - 2);
        const float u = tpos - (float)i;

        const float2 n0 = g_tab[b][i];
        const float2 n1 = g_tab[b][i + 1];
        const float m0 = n0.y * hstep;
        const float m1 = n1.y * hstep;
        const float d  = n1.x - n0.x;
        const float c2 = 3.f * d - 2.f * m0 - m1;
        const float c3 = m0 + m1 - 2.f * d;
        res[e] = fmaf(u, fmaf(u, fmaf(u, c3, c2), m0), n0.x);
    }
    *(float4*)(out + base) = make_float4(res[0], res[1], res[2], res[3]);
}

extern "C" void kernel_launch(void* const* d_in, const int* in_sizes, int n_in,
                              void* d_out, int out_size)
{
    // metadata order: x, wq, bq, wk, bk, wv, bv, conv_w, conv_b
    const float* x  = (const float*)d_in[0];
    const float* wq = (const float*)d_in[1];
    const float* bq = (const float*)d_in[2];
    const float* wk = (const float*)d_in[3];
    const float* bk = (const float*)d_in[4];
    const float* wv = (const float*)d_in[5];
    const float* bv = (const float*)d_in[6];
    const float* cw = (const float*)d_in[7];
    const float* cb = (const float*)d_in[8];
    float* out = (float*)d_out;

    gsa_prep_kernel<<<dim3(NSL + 1, NB), 256>>>(x, wk, bk, wv, bv, cw, cb);
    gsa_table_kernel<<<dim3(NPTS / 256, NB), 256>>>(wq, bq);
    gsa_query_kernel<<<dim3(HW / 1024, NB), 256>>>(x, wq, bq, out);
}

// round 4
// speedup vs baseline: 1.1359x; 1.1359x over previous
#include <cuda_runtime.h>
#include <cstdint>

// GSA_69063074119914 — scalar-channel spatial-reduction attention.
// Fully fused single-launch design: one 8-CTA cluster per batch.
//   Phase 1: slice scan (q-range) + conv -> (k,v) per CTA slice
//   Phase 2: per-batch f/f' table (1024 nodes) split across the cluster
//   Phase 3: cubic-Hermite query evaluation from local smem table
// Cross-CTA exchange via DSMEM (mapa + ld.shared::cluster).

#define NB    16
#define NC    8                 // CTAs per cluster (= per batch)
#define NT    256               // keys per batch
#define HW    16384             // queries per batch
#define NPTS  1024              // table nodes per batch
#define NODES_PER_CTA (NPTS/NC) // 128
#define CELLS_PER_CTA (NT/NC)   // 32
#define LOG2E 1.4426950408889634f
#define LN2   0.6931471805599453f

__device__ __forceinline__ uint32_t smem_u32(const void* p) {
    uint32_t a;
    asm("{ .reg .u64 t; cvta.to.shared.u64 t, %1; cvt.u32.u64 %0, t; }"
        : "=r"(a) : "l"(p));
    return a;
}
__device__ __forceinline__ uint32_t mapa_u32(uint32_t addr, uint32_t rank) {
    uint32_t r;
    asm("mapa.shared::cluster.u32 %0, %1, %2;" : "=r"(r) : "r"(addr), "r"(rank));
    return r;
}
__device__ __forceinline__ float ld_clu_f32(uint32_t a) {
    float v;
    asm volatile("ld.shared::cluster.f32 %0, [%1];" : "=f"(v) : "r"(a));
    return v;
}
#define CLUSTER_SYNC() do { \
    asm volatile("barrier.cluster.arrive.aligned;" ::: "memory"); \
    asm volatile("barrier.cluster.wait.aligned;"   ::: "memory"); \
} while (0)

__global__ void __launch_bounds__(256) __cluster_dims__(NC, 1, 1)
gsa_fused_kernel(const float* __restrict__ x,
                 const float* __restrict__ wq, const float* __restrict__ bq,
                 const float* __restrict__ wk, const float* __restrict__ bk,
                 const float* __restrict__ wv, const float* __restrict__ bv,
                 const float* __restrict__ cw, const float* __restrict__ cb,
                 float* __restrict__ out)
{
    __shared__ float  s_cw[64];
    __shared__ float  s_red[256];               // conv partials
    __shared__ float  s_mn[8], s_mx[8];         // warp x-range partials
    __shared__ float2 s_kvown[CELLS_PER_CTA];   // this CTA's (k2, v)
    __shared__ float4 s_partown;                // xmin, xmax, k2min, k2max
    __shared__ float2 s_kv[NT];                 // gathered full kv
    __shared__ float4 s_parts[NC];              // gathered partials
    __shared__ float4 s_half[NODES_PER_CTA];    // table upper-half sums
    __shared__ float2 s_tabown[NODES_PER_CTA];  // this CTA's table nodes
    __shared__ float2 s_tab[NPTS];              // gathered full table

    const int b    = blockIdx.y;
    const int rank = blockIdx.x;                // 0..NC-1 within cluster
    const int t    = threadIdx.x;
    const int lane = t & 31;
    const int warp = t >> 5;

    const float wq0 = wq[0], bq0 = bq[0];
    const float wk0 = wk[0], bk0 = bk[0];
    const float wv0 = wv[0], bv0 = bv[0];
    const float cb0 = cb[0];
    if (t < 64) s_cw[t] = cw[t];
    __syncthreads();

    // ===== Phase 1: slice load -> range scan + conv partials =====
    // Slice = x rows [16*rank, 16*rank+16). Thread t: rr = t>>4 (slice row),
    // oct = t&15 (8-float column segment). Segment == half a conv-patch row.
    const int rr  = t >> 4;
    const int oct = t & 15;
    const float* seg = x + (size_t)b * HW + (16 * rank + rr) * 128 + oct * 8;
    const float4 a0 = *(const float4*)(seg);
    const float4 a1 = *(const float4*)(seg + 4);

    // x min/max over 8 regs
    float mn = fminf(fminf(fminf(a0.x, a0.y), fminf(a0.z, a0.w)),
                     fminf(fminf(a1.x, a1.y), fminf(a1.z, a1.w)));
    float mx = fmaxf(fmaxf(fmaxf(a0.x, a0.y), fmaxf(a0.z, a0.w)),
                     fmaxf(fmaxf(a1.x, a1.y), fmaxf(a1.z, a1.w)));
#pragma unroll
    for (int off = 16; off > 0; off >>= 1) {
        mn = fminf(mn, __shfl_xor_sync(0xffffffffu, mn, off));
        mx = fmaxf(mx, __shfl_xor_sync(0xffffffffu, mx, off));
    }
    if (lane == 0) { s_mn[warp] = mn; s_mx[warp] = mx; }

    // conv partial for patch row p of cell (ci, oct), p = rr&7, ci = rr>>3
    {
        const int p = rr & 7;
        const float* cwp = s_cw + p * 8;
        float acc = a0.x * cwp[0];
        acc = fmaf(a0.y, cwp[1], acc);
        acc = fmaf(a0.z, cwp[2], acc);
        acc = fmaf(a0.w, cwp[3], acc);
        acc = fmaf(a1.x, cwp[4], acc);
        acc = fmaf(a1.y, cwp[5], acc);
        acc = fmaf(a1.z, cwp[6], acc);
        acc = fmaf(a1.w, cwp[7], acc);
        s_red[t] = acc;
    }
    __syncthreads();

    // threads 0..31: finish one cell each; reduce k2 min/max within warp 0
    if (t < CELLS_PER_CTA) {
        const int ci = t >> 4;     // 0..1
        const int j  = t & 15;     // 0..15
        float ds = cb0;
#pragma unroll
        for (int p = 0; p < 8; ++p)
            ds += s_red[ci * 128 + p * 16 + j];
        const float k2 = fmaf(wk0, ds, bk0) * LOG2E;
        const float v  = fmaf(wv0, ds, bv0);
        s_kvown[t] = make_float2(k2, v);

        float kmn = k2, kmx = k2;
#pragma unroll
        for (int off = 16; off > 0; off >>= 1) {
            kmn = fminf(kmn, __shfl_xor_sync(0xffffffffu, kmn, off));
            kmx = fmaxf(kmx, __shfl_xor_sync(0xffffffffu, kmx, off));
        }
        if (t == 0) {
            float rmn = s_mn[0], rmx = s_mx[0];
#pragma unroll
            for (int w = 1; w < 8; ++w) {
                rmn = fminf(rmn, s_mn[w]);
                rmx = fmaxf(rmx, s_mx[w]);
            }
            s_partown = make_float4(rmn, rmx, kmn, kmx);
        }
    }

    CLUSTER_SYNC();

    // ===== Gather kv + partials from all cluster CTAs =====
    {
        // kv: thread t fetches global cell t from owner CTA (t>>5)
        const uint32_t kv_base = smem_u32(s_kvown);
        const uint32_t src = mapa_u32(kv_base + (uint32_t)(t & 31) * 8u,
                                      (uint32_t)(t >> 5));
        const float kk = ld_clu_f32(src);
        const float vv = ld_clu_f32(src + 4);
        s_kv[t] = make_float2(kk, vv);

        if (t < NC) {
            const uint32_t pb = mapa_u32(smem_u32(&s_partown), (uint32_t)t);
            s_parts[t] = make_float4(ld_clu_f32(pb), ld_clu_f32(pb + 4),
                                     ld_clu_f32(pb + 8), ld_clu_f32(pb + 12));
        }
    }
    __syncthreads();

    // redundant final reduction of the 8 partials (registers, cheap)
    float xmn = s_parts[0].x, xmx = s_parts[0].y;
    float kmn = s_parts[0].z, kmx = s_parts[0].w;
#pragma unroll
    for (int i = 1; i < NC; ++i) {
        const float4 p = s_parts[i];
        xmn = fminf(xmn, p.x); xmx = fmaxf(xmx, p.y);
        kmn = fminf(kmn, p.z); kmx = fmaxf(kmx, p.w);
    }
    const float qa  = fmaf(wq0, xmn, bq0);
    const float qb  = fmaf(wq0, xmx, bq0);
    const float qlo = fminf(qa, qb);
    const float qhi = fmaxf(qa, qb);
    const float range = qhi - qlo;
    const float hstep = range * (1.0f / (NPTS - 1));
    const float scale = (range > 0.f) ? (NPTS - 1) / range : 0.f;

    // ===== Phase 2: table nodes [128*rank, 128*rank+128), 2 threads/node =====
    {
        const int nloc = t & 127;           // node within CTA
        const int half = t >> 7;            // key half: 0 or 1
        const float qn = fmaf(hstep, (float)(NODES_PER_CTA * rank + nloc), qlo);
        const float m2 = fmaxf(qn * kmx, qn * kmn);   // exact max exponent

        float S0 = 0.f, S1 = 0.f, S2 = 0.f, S3 = 0.f;
        const float2* kvh = s_kv + half * 128;
#pragma unroll 8
        for (int u = 0; u < 128; ++u) {
            const float2 kv = kvh[u];
            const float a = fmaf(qn, kv.x, -m2);
            float e;
            asm("ex2.approx.f32 %0, %1;" : "=f"(e) : "f"(a));
            const float ve = kv.y * e;
            S0 += e;
            S1 += ve;
            S2 = fmaf(kv.x, e,  S2);
            S3 = fmaf(kv.x, ve, S3);
        }
        if (half) s_half[nloc] = make_float4(S0, S1, S2, S3);
        __syncthreads();
        if (!half) {
            const float4 hs = s_half[nloc];
            const float T0 = S0 + hs.x, T1 = S1 + hs.y;
            const float T2 = S2 + hs.z, T3 = S3 + hs.w;
            const float r  = __frcp_rn(T0);
            const float f  = T1 * r;
            const float fp = LN2 * r * fmaf(-f, T2, T3);
            s_tabown[nloc] = make_float2(f, fp);
        }
    }

    CLUSTER_SYNC();

    // ===== Gather full table (own region read via cluster path too) =====
    {
        const uint32_t tb = smem_u32(s_tabown);
#pragma unroll
        for (int i = 0; i < 4; ++i) {
            const int g = t + i * 256;                       // global node
            const uint32_t src = mapa_u32(tb + (uint32_t)(g & 127) * 8u,
                                          (uint32_t)(g >> 7));
            const float f  = ld_clu_f32(src);
            const float fp = ld_clu_f32(src + 4);
            s_tab[g] = make_float2(f, fp);
        }
    }
    __syncthreads();
    CLUSTER_SYNC();   // all DSMEM reads complete before any CTA may retire

    // ===== Phase 3: evaluate this CTA's 2048 queries =====
    const size_t qbase = (size_t)b * HW + rank * 2048;
#pragma unroll
    for (int it = 0; it < 2; ++it) {
        const size_t off = qbase + it * 1024 + t * 4;
        const float4 xv = *(const float4*)(x + off);
        float qs[4] = { fmaf(wq0, xv.x, bq0), fmaf(wq0, xv.y, bq0),
                        fmaf(wq0, xv.z, bq0), fmaf(wq0, xv.w, bq0) };
        float res[4];
#pragma unroll
        for (int e = 0; e < 4; ++e) {
            float tpos = (qs[e] - qlo) * scale;
            tpos = fminf(fmaxf(tpos, 0.f), (float)(NPTS - 1));
            const int i = min((int)tpos, NPTS - 2);
            const float u = tpos - (float)i;
            const float2 n0 = s_tab[i];
            const float2 n1 = s_tab[i + 1];
            const float m0 = n0.y * hstep;
            const float m1 = n1.y * hstep;
            const float d  = n1.x - n0.x;
            const float c2 = 3.f * d - 2.f * m0 - m1;
            const float c3 = m0 + m1 - 2.f * d;
            res[e] = fmaf(u, fmaf(u, fmaf(u, c3, c2), m0), n0.x);
        }
        *(float4*)(out + off) = make_float4(res[0], res[1], res[2], res[3]);
    }
}

extern "C" void kernel_launch(void* const* d_in, const int* in_sizes, int n_in,
                              void* d_out, int out_size)
{
    // metadata order: x, wq, bq, wk, bk, wv, bv, conv_w, conv_b
    const float* x  = (const float*)d_in[0];
    const float* wq = (const float*)d_in[1];
    const float* bq = (const float*)d_in[2];
    const float* wk = (const float*)d_in[3];
    const float* bk = (const float*)d_in[4];
    const float* wv = (const float*)d_in[5];
    const float* bv = (const float*)d_in[6];
    const float* cw = (const float*)d_in[7];
    const float* cb = (const float*)d_in[8];
    float* out = (float*)d_out;

    gsa_fused_kernel<<<dim3(NC, NB), 256>>>(x, wq, bq, wk, bk, wv, bv, cw, cb, out);
}

// round 5
// speedup vs baseline: 1.2861x; 1.1322x over previous
#include <cuda_runtime.h>

// GSA_69063074119914 — scalar-channel spatial-reduction attention.
// Single launch, fully independent CTAs (no clusters, no cross-CTA traffic).
// Grid (8, 16): CTA = (slice r, batch b), 256 threads.
//   Phase 1: load own 2048-query slice into regs (q-range); redundantly
//            compute the FULL conv for batch b -> all 256 (k,v) + k-range.
//   Phase 2: 256-node f/f' table over the CTA-LOCAL q-range (exact softmax,
//            max-exponent via global k min/max).
//   Phase 3: cubic Hermite interpolation of the 8 in-register queries.

#define NB    16
#define NSLICE 8
#define HW    16384
#define NT    256      // keys per batch
#define NPL   256      // local table nodes per CTA
#define LOG2E 1.4426950408889634f
#define LN2   0.6931471805599453f

__global__ void __launch_bounds__(256) gsa_kernel(
        const float* __restrict__ x,
        const float* __restrict__ wq, const float* __restrict__ bq,
        const float* __restrict__ wk, const float* __restrict__ bk,
        const float* __restrict__ wv, const float* __restrict__ bv,
        const float* __restrict__ cw, const float* __restrict__ cb,
        float* __restrict__ out)
{
    __shared__ float s_cw[64];
    __shared__ __align__(16) float2 s_kv[NT];   // (k*log2e, v)
    __shared__ float2 s_tab[NPL];               // (f, f' * hstep)
    __shared__ float s_qmn[8], s_qmx[8], s_kmn[8], s_kmx[8];

    const int b    = blockIdx.y;
    const int r    = blockIdx.x;
    const int t    = threadIdx.x;
    const int lane = t & 31;
    const int warp = t >> 5;

    const float wq0 = wq[0], bq0 = bq[0];
    const float wk0 = wk[0], bk0 = bk[0];
    const float wv0 = wv[0], bv0 = bv[0];
    const float cb0 = cb[0];
    if (t < 64) s_cw[t] = cw[t];
    __syncthreads();

    const float* xb = x + (size_t)b * HW;

    // ===== Phase 1a: own query slice (rows [16r, 16r+16)) into registers =====
    const int rr  = t >> 4;            // slice row 0..15
    const int oct = t & 15;            // 8-float column segment
    const size_t segoff = (size_t)(16 * r + rr) * 128 + oct * 8;
    const float4 a0 = *(const float4*)(xb + segoff);
    const float4 a1 = *(const float4*)(xb + segoff + 4);

    float qv[8] = { fmaf(wq0, a0.x, bq0), fmaf(wq0, a0.y, bq0),
                    fmaf(wq0, a0.z, bq0), fmaf(wq0, a0.w, bq0),
                    fmaf(wq0, a1.x, bq0), fmaf(wq0, a1.y, bq0),
                    fmaf(wq0, a1.z, bq0), fmaf(wq0, a1.w, bq0) };
    float qmn = qv[0], qmx = qv[0];
#pragma unroll
    for (int e = 1; e < 8; ++e) {
        qmn = fminf(qmn, qv[e]);
        qmx = fmaxf(qmx, qv[e]);
    }
#pragma unroll
    for (int off = 16; off > 0; off >>= 1) {
        qmn = fminf(qmn, __shfl_xor_sync(0xffffffffu, qmn, off));
        qmx = fmaxf(qmx, __shfl_xor_sync(0xffffffffu, qmx, off));
    }
    if (lane == 0) { s_qmn[warp] = qmn; s_qmx[warp] = qmx; }

    // ===== Phase 1b: full conv for batch b (redundant per CTA) =====
    // Thread t -> cell (ci, cj); 16 independent LDG.128 (L2-resident mostly).
    const float* cbase = xb + (size_t)rr * 8 * 128 + oct * 8;  // ci=rr, cj=oct
    float ds = cb0;
#pragma unroll
    for (int p = 0; p < 8; ++p) {
        const float4 u0 = *(const float4*)(cbase + p * 128);
        const float4 u1 = *(const float4*)(cbase + p * 128 + 4);
        const float* w = s_cw + p * 8;
        ds = fmaf(u0.x, w[0], ds);
        ds = fmaf(u0.y, w[1], ds);
        ds = fmaf(u0.z, w[2], ds);
        ds = fmaf(u0.w, w[3], ds);
        ds = fmaf(u1.x, w[4], ds);
        ds = fmaf(u1.y, w[5], ds);
        ds = fmaf(u1.z, w[6], ds);
        ds = fmaf(u1.w, w[7], ds);
    }
    const float k2 = fmaf(wk0, ds, bk0) * LOG2E;
    const float vv = fmaf(wv0, ds, bv0);
    s_kv[t] = make_float2(k2, vv);

    float kmn = k2, kmx = k2;
#pragma unroll
    for (int off = 16; off > 0; off >>= 1) {
        kmn = fminf(kmn, __shfl_xor_sync(0xffffffffu, kmn, off));
        kmx = fmaxf(kmx, __shfl_xor_sync(0xffffffffu, kmx, off));
    }
    if (lane == 0) { s_kmn[warp] = kmn; s_kmx[warp] = kmx; }
    __syncthreads();

    // Redundant final reductions in registers (every thread needs them).
    float qlo = s_qmn[0], qhi = s_qmx[0];
    kmn = s_kmn[0]; kmx = s_kmx[0];
#pragma unroll
    for (int w = 1; w < 8; ++w) {
        qlo = fminf(qlo, s_qmn[w]);
        qhi = fmaxf(qhi, s_qmx[w]);
        kmn = fminf(kmn, s_kmn[w]);
        kmx = fmaxf(kmx, s_kmx[w]);
    }
    const float range = qhi - qlo;
    const float hstep = range * (1.0f / (NPL - 1));
    const float scale = (range > 0.f) ? (NPL - 1) / range : 0.f;

    // ===== Phase 2: local table, node t =====
    {
        const float qn = fmaf(hstep, (float)t, qlo);
        const float m2 = fmaxf(qn * kmx, qn * kmn);   // exact max exponent

        float S0a = 0.f, S1a = 0.f, S2a = 0.f, S3a = 0.f;
        float S0b = 0.f, S1b = 0.f, S2b = 0.f, S3b = 0.f;
#pragma unroll 4
        for (int u = 0; u < NT; u += 2) {
            const float4 kk = *(const float4*)(s_kv + u);   // 2 (k,v) pairs
            float e0, e1;
            const float x0 = fmaf(qn, kk.x, -m2);
            const float x1 = fmaf(qn, kk.z, -m2);
            asm("ex2.approx.f32 %0, %1;" : "=f"(e0) : "f"(x0));
            asm("ex2.approx.f32 %0, %1;" : "=f"(e1) : "f"(x1));
            const float ve0 = kk.y * e0;
            const float ve1 = kk.w * e1;
            S0a += e0;              S0b += e1;
            S1a += ve0;             S1b += ve1;
            S2a = fmaf(kk.x, e0,  S2a);  S2b = fmaf(kk.z, e1,  S2b);
            S3a = fmaf(kk.x, ve0, S3a);  S3b = fmaf(kk.z, ve1, S3b);
        }
        const float T0 = S0a + S0b, T1 = S1a + S1b;
        const float T2 = S2a + S2b, T3 = S3a + S3b;
        const float rcp = __frcp_rn(T0);
        const float f   = T1 * rcp;
        const float fp  = LN2 * rcp * fmaf(-f, T2, T3);   // df/dq
        s_tab[t] = make_float2(f, fp * hstep);            // tangent in u-space
    }
    __syncthreads();

    // ===== Phase 3: evaluate the 8 in-register queries =====
    float res[8];
#pragma unroll
    for (int e = 0; e < 8; ++e) {
        float tpos = (qv[e] - qlo) * scale;
        tpos = fminf(fmaxf(tpos, 0.f), (float)(NPL - 1));
        const int i = min((int)tpos, NPL - 2);
        const float u = tpos - (float)i;
        const float2 n0 = s_tab[i];
        const float2 n1 = s_tab[i + 1];
        const float d  = n1.x - n0.x;
        const float c2 = 3.f * d - 2.f * n0.y - n1.y;
        const float c3 = n0.y + n1.y - 2.f * d;
        res[e] = fmaf(u, fmaf(u, fmaf(u, c3, c2), n0.y), n0.x);
    }
    float* ob = out + (size_t)b * HW + segoff;
    *(float4*)(ob)     = make_float4(res[0], res[1], res[2], res[3]);
    *(float4*)(ob + 4) = make_float4(res[4], res[5], res[6], res[7]);
}

extern "C" void kernel_launch(void* const* d_in, const int* in_sizes, int n_in,
                              void* d_out, int out_size)
{
    // metadata order: x, wq, bq, wk, bk, wv, bv, conv_w, conv_b
    const float* x  = (const float*)d_in[0];
    const float* wq = (const float*)d_in[1];
    const float* bq = (const float*)d_in[2];
    const float* wk = (const float*)d_in[3];
    const float* bk = (const float*)d_in[4];
    const float* wv = (const float*)d_in[5];
    const float* bv = (const float*)d_in[6];
    const float* cw = (const float*)d_in[7];
    const float* cb = (const float*)d_in[8];
    float* out = (float*)d_out;

    gsa_kernel<<<dim3(NSLICE, NB), 256>>>(x, wq, bq, wk, bk, wv, bv, cw, cb, out);
}

// round 6
// speedup vs baseline: 1.5598x; 1.2128x over previous
#include <cuda_runtime.h>

// GSA_69063074119914 — scalar-channel spatial-reduction attention.
// Single launch, independent CTAs. Grid (8, 16): CTA = (slice r, batch b).
//   Phase 1: query slice -> regs (+local q-range); redundant full conv
//            (prefetched, MLP=8) -> all 256 (k,v) + global k-range.
//   Phase 2: 128-node local f/f' table, 2 threads/node (key halves).
//   Phase 3: cubic Hermite on the 8 in-register queries.

#define NB    16
#define NSLICE 8
#define HW    16384
#define NT    256      // keys per batch
#define NPL   128      // local table nodes per CTA
#define LOG2E 1.4426950408889634f
#define LN2   0.6931471805599453f

__global__ void __launch_bounds__(256) gsa_kernel(
        const float* __restrict__ x,
        const float* __restrict__ wq, const float* __restrict__ bq,
        const float* __restrict__ wk, const float* __restrict__ bk,
        const float* __restrict__ wv, const float* __restrict__ bv,
        const float* __restrict__ cw, const float* __restrict__ cb,
        float* __restrict__ out)
{
    __shared__ float s_cw[64];
    __shared__ __align__(16) float2 s_kv[NT];    // (k*log2e, v)
    __shared__ float4 s_half[NPL];               // upper-half partial sums
    __shared__ float2 s_tab[NPL];                // (f, f' * hstep)
    __shared__ float s_qmn[8], s_qmx[8], s_kmn[8], s_kmx[8];

    const int b    = blockIdx.y;
    const int r    = blockIdx.x;
    const int t    = threadIdx.x;
    const int lane = t & 31;
    const int warp = t >> 5;

    const float wq0 = wq[0], bq0 = bq[0];
    const float wk0 = wk[0], bk0 = bk[0];
    const float wv0 = wv[0], bv0 = bv[0];
    const float cb0 = cb[0];
    if (t < 64) s_cw[t] = cw[t];

    const float* xb = x + (size_t)b * HW;
    const int rr  = t >> 4;            // 0..15
    const int oct = t & 15;            // 0..15

    // ===== Phase 1a: own query slice (rows [16r,16r+16)) -> registers =====
    const size_t segoff = (size_t)(16 * r + rr) * 128 + oct * 8;
    const float4 a0 = *(const float4*)(xb + segoff);
    const float4 a1 = *(const float4*)(xb + segoff + 4);

    // ===== Phase 1b: prefetch conv patch (cell (rr,oct)) — 16 LDG.128 =====
    const float* cbase = xb + (size_t)rr * 8 * 128 + oct * 8;
    float4 u0 = *(const float4*)(cbase + 0 * 128);
    float4 u1 = *(const float4*)(cbase + 0 * 128 + 4);
    float4 u2 = *(const float4*)(cbase + 1 * 128);
    float4 u3 = *(const float4*)(cbase + 1 * 128 + 4);
    float4 u4 = *(const float4*)(cbase + 2 * 128);
    float4 u5 = *(const float4*)(cbase + 2 * 128 + 4);
    float4 u6 = *(const float4*)(cbase + 3 * 128);
    float4 u7 = *(const float4*)(cbase + 3 * 128 + 4);

    float qv[8] = { fmaf(wq0, a0.x, bq0), fmaf(wq0, a0.y, bq0),
                    fmaf(wq0, a0.z, bq0), fmaf(wq0, a0.w, bq0),
                    fmaf(wq0, a1.x, bq0), fmaf(wq0, a1.y, bq0),
                    fmaf(wq0, a1.z, bq0), fmaf(wq0, a1.w, bq0) };
    float qmn = qv[0], qmx = qv[0];
#pragma unroll
    for (int e = 1; e < 8; ++e) {
        qmn = fminf(qmn, qv[e]);
        qmx = fmaxf(qmx, qv[e]);
    }
#pragma unroll
    for (int off = 16; off > 0; off >>= 1) {
        qmn = fminf(qmn, __shfl_xor_sync(0xffffffffu, qmn, off));
        qmx = fmaxf(qmx, __shfl_xor_sync(0xffffffffu, qmx, off));
    }
    if (lane == 0) { s_qmn[warp] = qmn; s_qmx[warp] = qmx; }
    __syncthreads();   // also covers s_cw visibility

    // rows 0..3 with 4 accumulators
    float d0, d1, d2, d3;
    {
        const float* w = s_cw;
        d0 =       u0.x * w[0];
        d0 = fmaf(u0.y, w[1], d0);
        d0 = fmaf(u0.z, w[2], d0);
        d0 = fmaf(u0.w, w[3], d0);
        d0 = fmaf(u1.x, w[4], d0);
        d0 = fmaf(u1.y, w[5], d0);
        d0 = fmaf(u1.z, w[6], d0);
        d0 = fmaf(u1.w, w[7], d0);
        w = s_cw + 8;
        d1 =       u2.x * w[0];
        d1 = fmaf(u2.y, w[1], d1);
        d1 = fmaf(u2.z, w[2], d1);
        d1 = fmaf(u2.w, w[3], d1);
        d1 = fmaf(u3.x, w[4], d1);
        d1 = fmaf(u3.y, w[5], d1);
        d1 = fmaf(u3.z, w[6], d1);
        d1 = fmaf(u3.w, w[7], d1);
        w = s_cw + 16;
        d2 =       u4.x * w[0];
        d2 = fmaf(u4.y, w[1], d2);
        d2 = fmaf(u4.z, w[2], d2);
        d2 = fmaf(u4.w, w[3], d2);
        d2 = fmaf(u5.x, w[4], d2);
        d2 = fmaf(u5.y, w[5], d2);
        d2 = fmaf(u5.z, w[6], d2);
        d2 = fmaf(u5.w, w[7], d2);
        w = s_cw + 24;
        d3 =       u6.x * w[0];
        d3 = fmaf(u6.y, w[1], d3);
        d3 = fmaf(u6.z, w[2], d3);
        d3 = fmaf(u6.w, w[3], d3);
        d3 = fmaf(u7.x, w[4], d3);
        d3 = fmaf(u7.y, w[5], d3);
        d3 = fmaf(u7.z, w[6], d3);
        d3 = fmaf(u7.w, w[7], d3);
    }
    // rows 4..7 (reuse registers)
    u0 = *(const float4*)(cbase + 4 * 128);
    u1 = *(const float4*)(cbase + 4 * 128 + 4);
    u2 = *(const float4*)(cbase + 5 * 128);
    u3 = *(const float4*)(cbase + 5 * 128 + 4);
    u4 = *(const float4*)(cbase + 6 * 128);
    u5 = *(const float4*)(cbase + 6 * 128 + 4);
    u6 = *(const float4*)(cbase + 7 * 128);
    u7 = *(const float4*)(cbase + 7 * 128 + 4);
    {
        const float* w = s_cw + 32;
        d0 = fmaf(u0.x, w[0], d0);
        d0 = fmaf(u0.y, w[1], d0);
        d0 = fmaf(u0.z, w[2], d0);
        d0 = fmaf(u0.w, w[3], d0);
        d0 = fmaf(u1.x, w[4], d0);
        d0 = fmaf(u1.y, w[5], d0);
        d0 = fmaf(u1.z, w[6], d0);
        d0 = fmaf(u1.w, w[7], d0);
        w = s_cw + 40;
        d1 = fmaf(u2.x, w[0], d1);
        d1 = fmaf(u2.y, w[1], d1);
        d1 = fmaf(u2.z, w[2], d1);
        d1 = fmaf(u2.w, w[3], d1);
        d1 = fmaf(u3.x, w[4], d1);
        d1 = fmaf(u3.y, w[5], d1);
        d1 = fmaf(u3.z, w[6], d1);
        d1 = fmaf(u3.w, w[7], d1);
        w = s_cw + 48;
        d2 = fmaf(u4.x, w[0], d2);
        d2 = fmaf(u4.y, w[1], d2);
        d2 = fmaf(u4.z, w[2], d2);
        d2 = fmaf(u4.w, w[3], d2);
        d2 = fmaf(u5.x, w[4], d2);
        d2 = fmaf(u5.y, w[5], d2);
        d2 = fmaf(u5.z, w[6], d2);
        d2 = fmaf(u5.w, w[7], d2);
        w = s_cw + 56;
        d3 = fmaf(u6.x, w[0], d3);
        d3 = fmaf(u6.y, w[1], d3);
        d3 = fmaf(u6.z, w[2], d3);
        d3 = fmaf(u6.w, w[3], d3);
        d3 = fmaf(u7.x, w[4], d3);
        d3 = fmaf(u7.y, w[5], d3);
        d3 = fmaf(u7.z, w[6], d3);
        d3 = fmaf(u7.w, w[7], d3);
    }
    const float ds = (d0 + d1) + (d2 + d3) + cb0;
    const float k2 = fmaf(wk0, ds, bk0) * LOG2E;
    const float vv = fmaf(wv0, ds, bv0);
    s_kv[t] = make_float2(k2, vv);

    float kmn = k2, kmx = k2;
#pragma unroll
    for (int off = 16; off > 0; off >>= 1) {
        kmn = fminf(kmn, __shfl_xor_sync(0xffffffffu, kmn, off));
        kmx = fmaxf(kmx, __shfl_xor_sync(0xffffffffu, kmx, off));
    }
    if (lane == 0) { s_kmn[warp] = kmn; s_kmx[warp] = kmx; }
    __syncthreads();

    // Redundant final reductions in registers.
    float qlo = s_qmn[0], qhi = s_qmx[0];
    kmn = s_kmn[0]; kmx = s_kmx[0];
#pragma unroll
    for (int w = 1; w < 8; ++w) {
        qlo = fminf(qlo, s_qmn[w]);
        qhi = fmaxf(qhi, s_qmx[w]);
        kmn = fminf(kmn, s_kmn[w]);
        kmx = fmaxf(kmx, s_kmx[w]);
    }
    const float range = qhi - qlo;
    const float hstep = range * (1.0f / (NPL - 1));
    const float scale = (range > 0.f) ? (NPL - 1) / range : 0.f;

    // ===== Phase 2: local table, 2 threads per node (key halves) =====
    {
        const int nloc = t & (NPL - 1);
        const int half = t >> 7;
        const float qn = fmaf(hstep, (float)nloc, qlo);
        const float m2 = fmaxf(qn * kmx, qn * kmn);   // exact max exponent

        float S0a = 0.f, S1a = 0.f, S2a = 0.f, S3a = 0.f;
        float S0b = 0.f, S1b = 0.f, S2b = 0.f, S3b = 0.f;
        const float2* kvh = s_kv + half * 128;
#pragma unroll 4
        for (int u = 0; u < 128; u += 2) {
            const float4 kk = *(const float4*)(kvh + u);   // 2 (k,v) pairs
            float e0, e1;
            const float x0 = fmaf(qn, kk.x, -m2);
            const float x1 = fmaf(qn, kk.z, -m2);
            asm("ex2.approx.f32 %0, %1;" : "=f"(e0) : "f"(x0));
            asm("ex2.approx.f32 %0, %1;" : "=f"(e1) : "f"(x1));
            const float ve0 = kk.y * e0;
            const float ve1 = kk.w * e1;
            S0a += e0;              S0b += e1;
            S1a += ve0;             S1b += ve1;
            S2a = fmaf(kk.x, e0,  S2a);  S2b = fmaf(kk.z, e1,  S2b);
            S3a = fmaf(kk.x, ve0, S3a);  S3b = fmaf(kk.z, ve1, S3b);
        }
        const float P0 = S0a + S0b, P1 = S1a + S1b;
        const float P2 = S2a + S2b, P3 = S3a + S3b;
        if (half) s_half[nloc] = make_float4(P0, P1, P2, P3);
        __syncthreads();
        if (!half) {
            const float4 hs = s_half[nloc];
            const float T0 = P0 + hs.x, T1 = P1 + hs.y;
            const float T2 = P2 + hs.z, T3 = P3 + hs.w;
            const float rcp = __frcp_rn(T0);
            const float f   = T1 * rcp;
            const float fp  = LN2 * rcp * fmaf(-f, T2, T3);
            s_tab[nloc] = make_float2(f, fp * hstep);     // tangent in u-space
        }
    }
    __syncthreads();

    // ===== Phase 3: evaluate the 8 in-register queries =====
    float res[8];
#pragma unroll
    for (int e = 0; e < 8; ++e) {
        float tpos = (qv[e] - qlo) * scale;
        tpos = fminf(fmaxf(tpos, 0.f), (float)(NPL - 1));
        const int i = min((int)tpos, NPL - 2);
        const float u = tpos - (float)i;
        const float2 n0 = s_tab[i];
        const float2 n1 = s_tab[i + 1];
        const float d  = n1.x - n0.x;
        const float c2 = 3.f * d - 2.f * n0.y - n1.y;
        const float c3 = n0.y + n1.y - 2.f * d;
        res[e] = fmaf(u, fmaf(u, fmaf(u, c3, c2), n0.y), n0.x);
    }
    float* ob = out + (size_t)b * HW + segoff;
    *(float4*)(ob)     = make_float4(res[0], res[1], res[2], res[3]);
    *(float4*)(ob + 4) = make_float4(res[4], res[5], res[6], res[7]);
}

extern "C" void kernel_launch(void* const* d_in, const int* in_sizes, int n_in,
                              void* d_out, int out_size)
{
    // metadata order: x, wq, bq, wk, bk, wv, bv, conv_w, conv_b
    const float* x  = (const float*)d_in[0];
    const float* wq = (const float*)d_in[1];
    const float* bq = (const float*)d_in[2];
    const float* wk = (const float*)d_in[3];
    const float* bk = (const float*)d_in[4];
    const float* wv = (const float*)d_in[5];
    const float* bv = (const float*)d_in[6];
    const float* cw = (const float*)d_in[7];
    const float* cb = (const float*)d_in[8];
    float* out = (float*)d_out;

    gsa_kernel<<<dim3(NSLICE, NB), 256>>>(x, wq, bq, wk, bk, wv, bv, cw, cb, out);
}

// round 7
// speedup vs baseline: 1.9176x; 1.2294x over previous
#include <cuda_runtime.h>

// GSA_69063074119914 — scalar-channel spatial-reduction attention.
// Grid (16,16): CTA = (8-row slice r, batch b), 256 threads, 2 CTAs/SM.
//   Phase 1: 1024-query slice -> regs (+local q-range); redundant full conv
//            (prefetched, MLP=8) -> all 256 (k,v) + global k-range.
//   Phase 2: 64-node local f/f' table, 4 threads/node (64-key quarters).
//   Phase 3: cubic Hermite on the 4 in-register queries.

#define NB    16
#define NSLICE 16
#define HW    16384
#define NT    256      // keys per batch
#define NPL   64       // local table nodes per CTA
#define LOG2E 1.4426950408889634f
#define LN2   0.6931471805599453f

__global__ void __launch_bounds__(256, 2) gsa_kernel(
        const float* __restrict__ x,
        const float* __restrict__ wq, const float* __restrict__ bq,
        const float* __restrict__ wk, const float* __restrict__ bk,
        const float* __restrict__ wv, const float* __restrict__ bv,
        const float* __restrict__ cw, const float* __restrict__ cb,
        float* __restrict__ out)
{
    __shared__ float s_cw[64];
    __shared__ __align__(16) float2 s_kv[NT];    // (k*log2e, v)
    __shared__ float4 s_part[3][NPL];            // quarter partial sums
    __shared__ float2 s_tab[NPL];                // (f, f' * hstep)
    __shared__ float s_qmn[8], s_qmx[8], s_kmn[8], s_kmx[8];

    const int b    = blockIdx.y;
    const int r    = blockIdx.x;
    const int t    = threadIdx.x;
    const int lane = t & 31;
    const int warp = t >> 5;

    const float wq0 = wq[0], bq0 = bq[0];
    const float wk0 = wk[0], bk0 = bk[0];
    const float wv0 = wv[0], bv0 = bv[0];
    const float cb0 = cb[0];
    if (t < 64) s_cw[t] = cw[t];

    const float* xb = x + (size_t)b * HW;
    const int rr  = t >> 4;            // conv cell row 0..15
    const int oct = t & 15;            // conv cell col 0..15

    // ===== Phase 1a: own query slice (rows [8r, 8r+8)) -> registers =====
    // thread t: slice row t>>5 (8 rows x 32 thr), cols (t&31)*4 .. +3
    const size_t segoff = (size_t)(8 * r + (t >> 5)) * 128 + (size_t)(t & 31) * 4;
    const float4 a0 = *(const float4*)(xb + segoff);

    // ===== Phase 1b: prefetch conv patch rows 0..3 (8 LDG.128) =====
    const float* cbase = xb + (size_t)rr * 8 * 128 + oct * 8;
    float4 u0 = *(const float4*)(cbase + 0 * 128);
    float4 u1 = *(const float4*)(cbase + 0 * 128 + 4);
    float4 u2 = *(const float4*)(cbase + 1 * 128);
    float4 u3 = *(const float4*)(cbase + 1 * 128 + 4);
    float4 u4 = *(const float4*)(cbase + 2 * 128);
    float4 u5 = *(const float4*)(cbase + 2 * 128 + 4);
    float4 u6 = *(const float4*)(cbase + 3 * 128);
    float4 u7 = *(const float4*)(cbase + 3 * 128 + 4);

    float qv[4] = { fmaf(wq0, a0.x, bq0), fmaf(wq0, a0.y, bq0),
                    fmaf(wq0, a0.z, bq0), fmaf(wq0, a0.w, bq0) };
    float qmn = fminf(fminf(qv[0], qv[1]), fminf(qv[2], qv[3]));
    float qmx = fmaxf(fmaxf(qv[0], qv[1]), fmaxf(qv[2], qv[3]));
#pragma unroll
    for (int off = 16; off > 0; off >>= 1) {
        qmn = fminf(qmn, __shfl_xor_sync(0xffffffffu, qmn, off));
        qmx = fmaxf(qmx, __shfl_xor_sync(0xffffffffu, qmx, off));
    }
    if (lane == 0) { s_qmn[warp] = qmn; s_qmx[warp] = qmx; }
    __syncthreads();   // also covers s_cw visibility

    // rows 0..3 with 4 accumulators
    float d0, d1, d2, d3;
    {
        const float* w = s_cw;
        d0 =       u0.x * w[0];
        d0 = fmaf(u0.y, w[1], d0);
        d0 = fmaf(u0.z, w[2], d0);
        d0 = fmaf(u0.w, w[3], d0);
        d0 = fmaf(u1.x, w[4], d0);
        d0 = fmaf(u1.y, w[5], d0);
        d0 = fmaf(u1.z, w[6], d0);
        d0 = fmaf(u1.w, w[7], d0);
        w = s_cw + 8;
        d1 =       u2.x * w[0];
        d1 = fmaf(u2.y, w[1], d1);
        d1 = fmaf(u2.z, w[2], d1);
        d1 = fmaf(u2.w, w[3], d1);
        d1 = fmaf(u3.x, w[4], d1);
        d1 = fmaf(u3.y, w[5], d1);
        d1 = fmaf(u3.z, w[6], d1);
        d1 = fmaf(u3.w, w[7], d1);
        w = s_cw + 16;
        d2 =       u4.x * w[0];
        d2 = fmaf(u4.y, w[1], d2);
        d2 = fmaf(u4.z, w[2], d2);
        d2 = fmaf(u4.w, w[3], d2);
        d2 = fmaf(u5.x, w[4], d2);
        d2 = fmaf(u5.y, w[5], d2);
        d2 = fmaf(u5.z, w[6], d2);
        d2 = fmaf(u5.w, w[7], d2);
        w = s_cw + 24;
        d3 =       u6.x * w[0];
        d3 = fmaf(u6.y, w[1], d3);
        d3 = fmaf(u6.z, w[2], d3);
        d3 = fmaf(u6.w, w[3], d3);
        d3 = fmaf(u7.x, w[4], d3);
        d3 = fmaf(u7.y, w[5], d3);
        d3 = fmaf(u7.z, w[6], d3);
        d3 = fmaf(u7.w, w[7], d3);
    }
    // rows 4..7 (reuse registers)
    u0 = *(const float4*)(cbase + 4 * 128);
    u1 = *(const float4*)(cbase + 4 * 128 + 4);
    u2 = *(const float4*)(cbase + 5 * 128);
    u3 = *(const float4*)(cbase + 5 * 128 + 4);
    u4 = *(const float4*)(cbase + 6 * 128);
    u5 = *(const float4*)(cbase + 6 * 128 + 4);
    u6 = *(const float4*)(cbase + 7 * 128);
    u7 = *(const float4*)(cbase + 7 * 128 + 4);
    {
        const float* w = s_cw + 32;
        d0 = fmaf(u0.x, w[0], d0);
        d0 = fmaf(u0.y, w[1], d0);
        d0 = fmaf(u0.z, w[2], d0);
        d0 = fmaf(u0.w, w[3], d0);
        d0 = fmaf(u1.x, w[4], d0);
        d0 = fmaf(u1.y, w[5], d0);
        d0 = fmaf(u1.z, w[6], d0);
        d0 = fmaf(u1.w, w[7], d0);
        w = s_cw + 40;
        d1 = fmaf(u2.x, w[0], d1);
        d1 = fmaf(u2.y, w[1], d1);
        d1 = fmaf(u2.z, w[2], d1);
        d1 = fmaf(u2.w, w[3], d1);
        d1 = fmaf(u3.x, w[4], d1);
        d1 = fmaf(u3.y, w[5], d1);
        d1 = fmaf(u3.z, w[6], d1);
        d1 = fmaf(u3.w, w[7], d1);
        w = s_cw + 48;
        d2 = fmaf(u4.x, w[0], d2);
        d2 = fmaf(u4.y, w[1], d2);
        d2 = fmaf(u4.z, w[2], d2);
        d2 = fmaf(u4.w, w[3], d2);
        d2 = fmaf(u5.x, w[4], d2);
        d2 = fmaf(u5.y, w[5], d2);
        d2 = fmaf(u5.z, w[6], d2);
        d2 = fmaf(u5.w, w[7], d2);
        w = s_cw + 56;
        d3 = fmaf(u6.x, w[0], d3);
        d3 = fmaf(u6.y, w[1], d3);
        d3 = fmaf(u6.z, w[2], d3);
        d3 = fmaf(u6.w, w[3], d3);
        d3 = fmaf(u7.x, w[4], d3);
        d3 = fmaf(u7.y, w[5], d3);
        d3 = fmaf(u7.z, w[6], d3);
        d3 = fmaf(u7.w, w[7], d3);
    }
    const float ds = (d0 + d1) + (d2 + d3) + cb0;
    const float k2 = fmaf(wk0, ds, bk0) * LOG2E;
    const float vv = fmaf(wv0, ds, bv0);
    s_kv[t] = make_float2(k2, vv);

    float kmn = k2, kmx = k2;
#pragma unroll
    for (int off = 16; off > 0; off >>= 1) {
        kmn = fminf(kmn, __shfl_xor_sync(0xffffffffu, kmn, off));
        kmx = fmaxf(kmx, __shfl_xor_sync(0xffffffffu, kmx, off));
    }
    if (lane == 0) { s_kmn[warp] = kmn; s_kmx[warp] = kmx; }
    __syncthreads();

    // Redundant final reductions in registers.
    float qlo = s_qmn[0], qhi = s_qmx[0];
    kmn = s_kmn[0]; kmx = s_kmx[0];
#pragma unroll
    for (int w = 1; w < 8; ++w) {
        qlo = fminf(qlo, s_qmn[w]);
        qhi = fmaxf(qhi, s_qmx[w]);
        kmn = fminf(kmn, s_kmn[w]);
        kmx = fmaxf(kmx, s_kmx[w]);
    }
    const float range = qhi - qlo;
    const float hstep = range * (1.0f / (NPL - 1));
    const float scale = (range > 0.f) ? (NPL - 1) / range : 0.f;

    // ===== Phase 2: local table, 4 threads per node (64-key quarters) =====
    {
        const int nloc = t & (NPL - 1);
        const int quar = t >> 6;            // 0..3
        const float qn = fmaf(hstep, (float)nloc, qlo);
        const float m2 = fmaxf(qn * kmx, qn * kmn);   // exact max exponent

        float S0a = 0.f, S1a = 0.f, S2a = 0.f, S3a = 0.f;
        float S0b = 0.f, S1b = 0.f, S2b = 0.f, S3b = 0.f;
        const float2* kvh = s_kv + quar * 64;
#pragma unroll 4
        for (int u = 0; u < 64; u += 2) {
            const float4 kk = *(const float4*)(kvh + u);   // 2 (k,v) pairs
            float e0, e1;
            const float x0 = fmaf(qn, kk.x, -m2);
            const float x1 = fmaf(qn, kk.z, -m2);
            asm("ex2.approx.f32 %0, %1;" : "=f"(e0) : "f"(x0));
            asm("ex2.approx.f32 %0, %1;" : "=f"(e1) : "f"(x1));
            const float ve0 = kk.y * e0;
            const float ve1 = kk.w * e1;
            S0a += e0;              S0b += e1;
            S1a += ve0;             S1b += ve1;
            S2a = fmaf(kk.x, e0,  S2a);  S2b = fmaf(kk.z, e1,  S2b);
            S3a = fmaf(kk.x, ve0, S3a);  S3b = fmaf(kk.z, ve1, S3b);
        }
        const float P0 = S0a + S0b, P1 = S1a + S1b;
        const float P2 = S2a + S2b, P3 = S3a + S3b;
        if (quar) s_part[quar - 1][nloc] = make_float4(P0, P1, P2, P3);
        __syncthreads();
        if (!quar) {
            const float4 h1 = s_part[0][nloc];
            const float4 h2 = s_part[1][nloc];
            const float4 h3 = s_part[2][nloc];
            const float T0 = (P0 + h1.x) + (h2.x + h3.x);
            const float T1 = (P1 + h1.y) + (h2.y + h3.y);
            const float T2 = (P2 + h1.z) + (h2.z + h3.z);
            const float T3 = (P3 + h1.w) + (h2.w + h3.w);
            const float rcp = __frcp_rn(T0);
            const float f   = T1 * rcp;
            const float fp  = LN2 * rcp * fmaf(-f, T2, T3);
            s_tab[nloc] = make_float2(f, fp * hstep);     // tangent in u-space
        }
    }
    __syncthreads();

    // ===== Phase 3: evaluate the 4 in-register queries =====
    float res[4];
#pragma unroll
    for (int e = 0; e < 4; ++e) {
        float tpos = (qv[e] - qlo) * scale;
        tpos = fminf(fmaxf(tpos, 0.f), (float)(NPL - 1));
        const int i = min((int)tpos, NPL - 2);
        const float u = tpos - (float)i;
        const float2 n0 = s_tab[i];
        const float2 n1 = s_tab[i + 1];
        const float d  = n1.x - n0.x;
        const float c2 = 3.f * d - 2.f * n0.y - n1.y;
        const float c3 = n0.y + n1.y - 2.f * d;
        res[e] = fmaf(u, fmaf(u, fmaf(u, c3, c2), n0.y), n0.x);
    }
    *(float4*)(out + (size_t)b * HW + segoff) =
        make_float4(res[0], res[1], res[2], res[3]);
}

extern "C" void kernel_launch(void* const* d_in, const int* in_sizes, int n_in,
                              void* d_out, int out_size)
{
    // metadata order: x, wq, bq, wk, bk, wv, bv, conv_w, conv_b
    const float* x  = (const float*)d_in[0];
    const float* wq = (const float*)d_in[1];
    const float* bq = (const float*)d_in[2];
    const float* wk = (const float*)d_in[3];
    const float* bk = (const float*)d_in[4];
    const float* wv = (const float*)d_in[5];
    const float* bv = (const float*)d_in[6];
    const float* cw = (const float*)d_in[7];
    const float* cb = (const float*)d_in[8];
    float* out = (float*)d_out;

    gsa_kernel<<<dim3(NSLICE, NB), 256>>>(x, wq, bq, wk, bk, wv, bv, cw, cb, out);
}